// round 15
// baseline (speedup 1.0000x reference)
#include <cuda_runtime.h>

// Problem constants (fixed by the benchmark)
#define NN     50000
#define KK     10
#define K1     11
#define EMAX   800000
#define NTHR   512
#define RT     40
#define NTILES 1250      // NN / RT exact
#define NBLK   296       // persistent grid: 2 blocks/SM x 148 SMs

// dynamic smem layout (bytes)
#define S_X0   0u        // X tile buf: 40 rows x 256B
#define S_X1   10240u
#define S_H0   20480u
#define S_H1   30720u
#define S_PA   40960u    // A partials: 2 k-half float planes (40x64 f32 each)
#define S_PB   61440u    // B partials: 2 planes
#define S_CB   81920u    // b1(64) b2(64) fcw(64)
// overlays (init / cold path only):
#define S_W1I  40960u    // W1 k-pair image 16KB (inside PA region)
#define S_W2I  61440u    // W2 image (inside PB region)
#define S_CP   61440u    // cold-path partial ull plane (10240)
#define S_R    71680u    // cold-path fc partials (5120)
#define DYNSMEM 82944

typedef unsigned long long ull;

// ---------------- device scratch (static, zero-initialized) ----------------
__device__ float g_wE[EMAX];
__device__ int   g_deg[NN];
__device__ float g_dinv[NN];
__device__ float g_y0[NN * 64];
__device__ float g_y1[NN * 64];
__device__ float g_acc[NN * 64];
__device__ float g_h[NN * 64];
__device__ unsigned g_bar_cnt;
__device__ volatile unsigned g_bar_gen;
__device__ unsigned g_tick;
__device__ unsigned g_done;

__device__ __constant__ float c_binom[K1][K1] = {
    {1,0,0,0,0,0,0,0,0,0,0},
    {1,1,0,0,0,0,0,0,0,0,0},
    {1,2,1,0,0,0,0,0,0,0,0},
    {1,3,3,1,0,0,0,0,0,0,0},
    {1,4,6,4,1,0,0,0,0,0,0},
    {1,5,10,10,5,1,0,0,0,0,0},
    {1,6,15,20,15,6,1,0,0,0,0},
    {1,7,21,35,35,21,7,1,0,0,0},
    {1,8,28,56,70,56,28,8,1,0,0},
    {1,9,36,84,126,126,84,36,9,1,0},
    {1,10,45,120,210,252,210,120,45,10,1}
};

// ---------------------------- PTX helpers -----------------------------------
__device__ __forceinline__ ull ffma2(ull a, ull b, ull c) {
    ull d;
    asm("fma.rn.f32x2 %0, %1, %2, %3;" : "=l"(d) : "l"(a), "l"(b), "l"(c));
    return d;
}
__device__ __forceinline__ ull pack2(float lo, float hi) {
    ull d;
    asm("mov.b64 %0, {%1, %2};" : "=l"(d) : "f"(lo), "f"(hi));
    return d;
}
__device__ __forceinline__ float2 unpack2(ull v) {
    float lo, hi;
    asm("mov.b64 {%0, %1}, %2;" : "=f"(lo), "=f"(hi) : "l"(v));
    return make_float2(lo, hi);
}
__device__ __forceinline__ float hsum2(ull v) {
    float a, b;
    asm("mov.b64 {%0, %1}, %2;" : "=f"(a), "=f"(b) : "l"(v));
    return a + b;
}
__device__ __forceinline__ void lds_2x64(ull &a, ull &b, unsigned addr) {
    asm volatile("ld.shared.v2.u64 {%0, %1}, [%2];" : "=l"(a), "=l"(b) : "r"(addr));
}
__device__ __forceinline__ ull lds64(unsigned addr) {
    ull v;
    asm volatile("ld.shared.u64 %0, [%1];" : "=l"(v) : "r"(addr));
    return v;
}
__device__ __forceinline__ void sts64(unsigned addr, ull v) {
    asm volatile("st.shared.u64 [%0], %1;" :: "r"(addr), "l"(v) : "memory");
}
__device__ __forceinline__ void sts32(unsigned addr, float v) {
    asm volatile("st.shared.f32 [%0], %1;" :: "r"(addr), "f"(v) : "memory");
}
__device__ __forceinline__ void cp16(unsigned dst, const float* src) {
    asm volatile("cp.async.ca.shared.global [%0], [%1], 16;" :: "r"(dst), "l"(src) : "memory");
}
__device__ __forceinline__ void cp_commit() {
    asm volatile("cp.async.commit_group;" ::: "memory");
}

// ---------------------------------------------------------------------------
// Grid barrier over exactly NBLK blocks (2/SM guaranteed by launch bounds +
// 83KB smem). Cold path only.
// ---------------------------------------------------------------------------
__device__ __forceinline__ void gbar() {
    __syncthreads();
    if (threadIdx.x == 0) {
        unsigned gen = g_bar_gen;
        __threadfence();
        if (atomicAdd(&g_bar_cnt, 1u) == (unsigned)(NBLK - 1)) {
            g_bar_cnt = 0u;
            __threadfence();
            g_bar_gen = gen + 1u;
        } else {
            while (g_bar_gen == gen) { }
            __threadfence();
        }
    }
    __syncthreads();
}

// ---------------------------------------------------------------------------
// Bernstein -> monomial coefficients (exact dyadic arithmetic); tid<32 lanes.
// ---------------------------------------------------------------------------
__device__ __forceinline__ void compute_coeffs(const float* __restrict__ coe,
                                               float* s_a, int* s_need, int tid) {
    if (tid < 32) {
        int m = tid;
        float a = 0.0f;
        if (m <= KK) {
            for (int j = 0; j <= KK; j++) {
                float cj = coe[j];
                cj = cj > 0.0f ? cj : 0.0f;
                float Bv = 0.0f;
                for (int p = 0; p <= j && p <= m; p++) {
                    int q = m - p;
                    if (q > KK - j) continue;
                    float t = c_binom[j][p] * c_binom[KK - j][q];
                    Bv += (p & 1) ? -t : t;
                }
                a += cj * (c_binom[KK][j] * (1.0f / 1024.0f)) * Bv;
            }
            s_a[m] = a;
        }
        unsigned msk = __ballot_sync(0xffffffffu, (m >= 1 && m <= KK && a != 0.0f));
        if (m == 0) *s_need = msk ? 1 : 0;
    }
}

// ---------------------------------------------------------------------------
// Staging helpers.
// ---------------------------------------------------------------------------
__device__ __forceinline__ void stage_x(const float* __restrict__ X, int row0,
                                        unsigned sxb, int tid) {
    {
        int row = tid >> 4, ch = tid & 15;
        cp16(sxb + row * 256 + ch * 16, X + (row0 + row) * 64 + ch * 4);
    }
    if (tid < 128) {
        int q = tid + NTHR;
        int row = q >> 4, ch = q & 15;
        cp16(sxb + row * 256 + ch * 16, X + (row0 + row) * 64 + ch * 4);
    }
}
__device__ __forceinline__ void stage_w_image(const float* __restrict__ W, float s,
                                              unsigned base, int tid) {
#pragma unroll
    for (int it = 0; it < 4; it++) {
        int idx = tid + it * NTHR;
        int j2 = idx >> 6, c = idx & 63;
        sts64(base + (unsigned)idx * 8u,
              pack2(W[2 * j2 * 64 + c] * s, W[(2 * j2 + 1) * 64 + c] * s));
    }
}

// ---------------------------------------------------------------------------
// Fast-path core: 1 col, 20 rows, one k-half. xrow includes h*128.
// Partial stored per row immediately (2 live accumulators).
// ---------------------------------------------------------------------------
__device__ __forceinline__ void core20(unsigned xrow, const ull wr[16],
                                       unsigned pout) {
#pragma unroll 2
    for (int r = 0; r < 20; r++) {
        ull a0 = 0ull, a1 = 0ull;
#pragma unroll
        for (int j = 0; j < 8; j++) {
            ull x01, x23;
            lds_2x64(x01, x23, xrow + (unsigned)(r * 256 + j * 16));
            a0 = ffma2(x01, wr[2 * j],     a0);
            a1 = ffma2(x23, wr[2 * j + 1], a1);
        }
        sts32(pout + (unsigned)(r * 256), hsum2(a0) + hsum2(a1));
    }
}

// ---------------------------------------------------------------------------
// Cold path (arbitrary coe): __noinline__ so its register pressure/spills
// cannot poison the fast path.
// ---------------------------------------------------------------------------
__device__ __noinline__ void poly_phase(const float* __restrict__ xin,
                                        const int* __restrict__ src,
                                        const int* __restrict__ dst,
                                        int e, int gt, int gsz, const float* sa) {
    float a0v = sa[0];
    for (int i = gt; i < NN * 64; i += gsz) g_acc[i] = a0v * xin[i];
    const float* yin = xin;
    float* yout = g_y0;
    float* yoth = g_y1;
    for (int m = 1; m <= KK; m++) {
        for (int i = gt; i < NN * 64; i += gsz) yout[i] = 0.0f;
        gbar();
        int tot = e * 32;
        for (int t = gt; t < tot; t += gsz) {
            int ed = t >> 5;
            int l = (t & 31) << 1;
            float w = g_wE[ed];
            int s = src[ed], d = dst[ed];
            float2 v = *(const float2*)(yin + s * 64 + l);
            atomicAdd(&yout[d * 64 + l],     w * v.x);
            atomicAdd(&yout[d * 64 + l + 1], w * v.y);
        }
        gbar();
        float am = sa[m];
        for (int i = gt; i < NN * 64; i += gsz) g_acc[i] += am * yout[i];
        yin = yout;
        float* t2 = yout; yout = yoth; yoth = t2;
    }
    gbar();
}

__device__ __noinline__ void gemm_pass_cold(
    const float* __restrict__ Xsrc,
    const float* __restrict__ W,
    const float* __restrict__ bias,
    const float* __restrict__ fcw, const float* __restrict__ fcb,
    float* __restrict__ Hout, float* __restrict__ out,
    int mode, unsigned sb, float* __restrict__ sred, int tid)
{
    const int cp = tid & 31;
    const int h  = (tid >> 5) & 1;
    const int rg = tid >> 6;

    stage_w_image(W, 1.0f, sb + S_W1I, tid);
    __syncthreads();

    ull wr[32];
    {
        unsigned wb = sb + S_W1I + (unsigned)(h * 16) * 512u + (unsigned)cp * 16u;
#pragma unroll
        for (int j = 0; j < 8; j++) {
            lds_2x64(wr[4 * j + 0], wr[4 * j + 1], wb + (unsigned)(2 * j) * 512u);
            lds_2x64(wr[4 * j + 2], wr[4 * j + 3], wb + (unsigned)(2 * j + 1) * 512u);
        }
    }
    const float2 bv = ((const float2*)bias)[cp];
    float2 fwv = make_float2(0.0f, 0.0f);
    float fb = 0.0f;
    if (mode) { fwv = ((const float2*)fcw)[cp]; fb = fcb[0]; }

    int t = blockIdx.x;
    int p = 0;
    if (t < NTILES) { stage_x(Xsrc, t * RT, sb + S_X0, tid); cp_commit(); }
    for (; t < NTILES; t += NBLK) {
        int tn = t + NBLK;
        bool hn = tn < NTILES;
        if (hn) { stage_x(Xsrc, tn * RT, sb + (p ? S_X0 : S_X1), tid); cp_commit(); }
        if (hn) asm volatile("cp.async.wait_group 1;" ::: "memory");
        else    asm volatile("cp.async.wait_group 0;" ::: "memory");
        __syncthreads();

        const unsigned xrow = sb + (p ? S_X1 : S_X0)
                            + (unsigned)(rg * 5) * 256u + (unsigned)(h * 128);
        ull acc[10];
#pragma unroll
        for (int i = 0; i < 10; i++) acc[i] = 0ull;
#pragma unroll
        for (int j = 0; j < 8; j++) {
#pragma unroll
            for (int r = 0; r < 5; r++) {
                ull x01, x23;
                lds_2x64(x01, x23, xrow + r * 256 + j * 16);
                acc[r * 2 + 0] = ffma2(x01, wr[4 * j + 0], acc[r * 2 + 0]);
                acc[r * 2 + 1] = ffma2(x01, wr[4 * j + 1], acc[r * 2 + 1]);
                acc[r * 2 + 0] = ffma2(x23, wr[4 * j + 2], acc[r * 2 + 0]);
                acc[r * 2 + 1] = ffma2(x23, wr[4 * j + 3], acc[r * 2 + 1]);
            }
        }
        if (h) {
#pragma unroll
            for (int r = 0; r < 5; r++)
                sts64(sb + S_CP + (unsigned)((rg * 5 + r) * 64 + 2 * cp) * 4u,
                      pack2(hsum2(acc[r * 2 + 0]), hsum2(acc[r * 2 + 1])));
        }
        __syncthreads();
        if (!h) {
#pragma unroll
            for (int r = 0; r < 5; r++) {
                float2 o = unpack2(lds64(sb + S_CP
                              + (unsigned)((rg * 5 + r) * 64 + 2 * cp) * 4u));
                float sx = hsum2(acc[r * 2 + 0]) + o.x + bv.x;
                float sy = hsum2(acc[r * 2 + 1]) + o.y + bv.y;
                if (mode == 0) {
                    float2 hv;
                    hv.x = fmaxf(sx, 0.0f);
                    hv.y = fmaxf(sy, 0.0f);
                    *(float2*)(Hout + (size_t)(t * RT + rg * 5 + r) * 64 + 2 * cp) = hv;
                } else {
                    float pr = fmaxf(sx, 0.0f) * fwv.x + fmaxf(sy, 0.0f) * fwv.y;
                    sts32(sb + S_R + (unsigned)((rg * 5 + r) * 32 + cp) * 4u, pr);
                }
            }
        }
        if (mode) {
            __syncthreads();
            if (tid < RT) {
                const float4* rp = (const float4*)(sred + tid * 32);
                float s = fb;
#pragma unroll
                for (int q4 = 0; q4 < 8; q4++) {
                    float4 v = rp[q4];
                    s += v.x + v.y + v.z + v.w;
                }
                out[t * RT + tid] = s;
            }
        }
        __syncthreads();
        p ^= 1;
    }
}

__device__ __noinline__ void cold_path(
    const float* x, const int* src, const int* dst, int e,
    const float* W1, const float* b1,
    const float* W2, const float* b2,
    const float* fcw, const float* fcb,
    float* out, const float* s_a, unsigned sb, float* sred)
{
    const int tid = threadIdx.x;
    const int gt  = blockIdx.x * NTHR + tid;
    const int gsz = NBLK * NTHR;

    for (int i = gt; i < NN; i += gsz) g_deg[i] = 0;
    gbar();
    for (int t = gt; t < e; t += gsz) atomicAdd(&g_deg[src[t]], 1);
    gbar();
    for (int i = gt; i < NN; i += gsz) {
        int d = g_deg[i];
        g_dinv[i] = d > 0 ? rsqrtf((float)d) : 0.0f;
    }
    gbar();
    for (int t = gt; t < e; t += gsz) g_wE[t] = g_dinv[src[t]] * g_dinv[dst[t]];
    gbar();

    poly_phase(x, src, dst, e, gt, gsz, s_a);
    gemm_pass_cold(g_acc, W1, b1, fcw, fcb, g_h, out, 0, sb, sred, tid);
    gbar();
    poly_phase(g_h, src, dst, e, gt, gsz, s_a);
    gemm_pass_cold(g_acc, W2, b2, fcw, fcb, (float*)0, out, 1, sb, sred, tid);
}

// ---------------------------------------------------------------------------
// Kernel: single launch, 296 persistent blocks (2/SM).
// Fast path: warp-specialized pipeline, 1-col threads (32-reg W footprint).
//   A group (warps 0-7):  core20(tA) -> PA; bar1; combine -> H[parity]
//   B group (warps 8-15): core20(tB from H[parity^1]) -> PB; bar2; fc -> out
// ---------------------------------------------------------------------------
__global__ __launch_bounds__(NTHR, 2) void bernnet(
    const float* __restrict__ x,
    const int*   __restrict__ src,
    const int*   __restrict__ dst,
    int e,
    const float* __restrict__ coe,
    const float* __restrict__ W1, const float* __restrict__ b1,
    const float* __restrict__ W2, const float* __restrict__ b2,
    const float* __restrict__ fcw, const float* __restrict__ fcb,
    float* __restrict__ out)
{
    extern __shared__ __align__(16) char dsm[];
    const unsigned sb = (unsigned)__cvta_generic_to_shared(dsm);
    __shared__ float s_a[K1];
    __shared__ int   s_need;
    __shared__ int   s_tk[2];

    const int tid = threadIdx.x;

    compute_coeffs(coe, s_a, &s_need, tid);
    __syncthreads();

    if (s_need) {
        cold_path(x, src, dst, e, W1, b1, W2, b2, fcw, fcb, out, s_a, sb,
                  (float*)(dsm + S_R));
        return;
    }

    // ===================== fast path: p(A) = a0*I ==========================
    const float a0 = s_a[0];

    stage_w_image(W1, a0, sb + S_W1I, tid);
    stage_w_image(W2, a0, sb + S_W2I, tid);
    {
        float* scb = (float*)(dsm + S_CB);
        if (tid < 64)       scb[tid] = b1[tid];
        else if (tid < 128) scb[tid] = b2[tid - 64];
        else if (tid < 192) scb[tid] = fcw[tid - 128];
    }
    if (tid == 0) s_tk[0] = (int)atomicAdd(&g_tick, 1u);
    __syncthreads();

    const int group = tid >> 8;            // 0: layer1 (A), 1: layer2+fc (B)
    const int gt    = tid & 255;
    const int c     = gt & 63;             // column
    const int h2    = (gt >> 6) & 1;       // k-half
    const int rgrp  = gt >> 7;             // 0/1 -> rows rgrp*20..+19
    const int lane  = tid & 31;
    const int gw    = (tid >> 5) & 7;      // warp within group

    // W column c, this k-half, into 16 ull registers (32 regs)
    ull wr[16];
    {
        unsigned wib = sb + (group ? S_W2I : S_W1I);
#pragma unroll
        for (int j = 0; j < 16; j++)
            wr[j] = lds64(wib + (unsigned)(((h2 * 16 + j) * 64 + c) * 8));
    }
    const float2* scb2 = (const float2*)(dsm + S_CB);
    const float fb = fcb[0];
    const unsigned coreoff = (unsigned)(rgrp * 20) * 256u + (unsigned)(h2 * 128);
    const unsigned poff    = (unsigned)(h2 * 10240) + (unsigned)(rgrp * 20) * 256u
                           + (unsigned)c * 4u;
    __syncthreads();   // wr loads complete before PA/PB planes are overwritten

    int tA = -1, tB = -1;
    int it = 0;
    for (;;) {
        const int tS = s_tk[it & 1];
        const bool sv = (tS < NTILES);
        if (!sv && tA < 0 && tB < 0) break;

        if (tid == 0)
            s_tk[(it + 1) & 1] = sv ? (int)atomicAdd(&g_tick, 1u) : NTILES;
        if (sv) { stage_x(x, tS * RT, sb + ((it & 1) ? S_X1 : S_X0), tid); }
        cp_commit();

        const unsigned pu = (unsigned)(it & 1);
        const unsigned Xr = sb + (pu ? S_X0 : S_X1);          // staged last iter
        const unsigned Hw = sb + S_H0 + pu * 10240u;
        const unsigned Hr = sb + S_H0 + (pu ^ 1u) * 10240u;

        if (group == 0) {
            if (tA >= 0) {
                core20(Xr + coreoff, wr, sb + S_PA + poff);
                asm volatile("bar.sync 1, 256;" ::: "memory");
#pragma unroll
                for (int j = 0; j < 5; j++) {
                    unsigned o = (unsigned)((5 * gw + j) * 256 + lane * 8);
                    float2 u = unpack2(lds64(sb + S_PA + o));
                    float2 v = unpack2(lds64(sb + S_PA + 10240u + o));
                    float2 b = scb2[lane];
                    sts64(Hw + o, pack2(fmaxf(u.x + v.x + b.x, 0.0f),
                                        fmaxf(u.y + v.y + b.y, 0.0f)));
                }
            }
        } else {
            if (tB >= 0) {
                core20(Hr + coreoff, wr, sb + S_PB + poff);
                asm volatile("bar.sync 2, 256;" ::: "memory");
                float pr[5];
#pragma unroll
                for (int j = 0; j < 5; j++) {
                    unsigned o = (unsigned)((5 * gw + j) * 256 + lane * 8);
                    float2 u = unpack2(lds64(sb + S_PB + o));
                    float2 v = unpack2(lds64(sb + S_PB + 10240u + o));
                    float2 b = scb2[32 + lane];
                    float2 fw = scb2[64 + lane];
                    pr[j] = fmaxf(u.x + v.x + b.x, 0.0f) * fw.x
                          + fmaxf(u.y + v.y + b.y, 0.0f) * fw.y;
                }
#pragma unroll
                for (int off = 16; off; off >>= 1)
#pragma unroll
                    for (int j = 0; j < 5; j++)
                        pr[j] += __shfl_xor_sync(0xffffffffu, pr[j], off);
                if (lane == 0) {
#pragma unroll
                    for (int j = 0; j < 5; j++)
                        out[tB * RT + 5 * gw + j] = pr[j] + fb;
                }
            }
        }

        asm volatile("cp.async.wait_group 0;" ::: "memory");
        __syncthreads();
        tB = tA;
        tA = sv ? tS : -1;
        it++;
    }

    // reset dynamic scheduler for the next (graph-replayed) launch
    if (tid == 0) {
        __threadfence();
        if (atomicAdd(&g_done, 1u) == (unsigned)(NBLK - 1)) {
            g_tick = 0u;
            g_done = 0u;
            __threadfence();
        }
    }
}

// ---------------------------------------------------------------------------
extern "C" void kernel_launch(void* const* d_in, const int* in_sizes, int n_in,
                              void* d_out, int out_size) {
    const float* x   = (const float*)d_in[0];
    const int*   ei  = (const int*)d_in[1];
    const float* coe = (const float*)d_in[2];
    const float* W1  = (const float*)d_in[3];
    const float* b1  = (const float*)d_in[4];
    const float* W2  = (const float*)d_in[5];
    const float* b2  = (const float*)d_in[6];
    const float* fcw = (const float*)d_in[7];
    const float* fcb = (const float*)d_in[8];
    float* out = (float*)d_out;

    int e = in_sizes[1] / 2;
    const int* src = ei;
    const int* dst = ei + e;

    static int smem_set = 0;
    if (!smem_set) {
        cudaFuncSetAttribute(bernnet, cudaFuncAttributeMaxDynamicSharedMemorySize,
                             DYNSMEM);
        smem_set = 1;
    }

    bernnet<<<NBLK, NTHR, DYNSMEM>>>(x, src, dst, e, coe,
                                     W1, b1, W2, b2, fcw, fcb, out);
}

// round 16
// speedup vs baseline: 1.2452x; 1.2452x over previous
#include <cuda_runtime.h>

// Problem constants (fixed by the benchmark)
#define NN     50000
#define KK     10
#define K1     11
#define EMAX   800000
#define NTHR   512
#define RT     40
#define NTILES 1250      // NN / RT exact
#define NBLK   148       // persistent grid (one wave)

// dynamic smem layout (bytes)
#define S_X0   0u        // X tile buf: 40 rows x 256B
#define S_X1   10240u
#define S_H0   20480u
#define S_H1   30720u
#define S_PA   40960u    // A partials: 4 k-quarter planes x 10240
#define S_PB   81920u    // B partials: 4 planes
#define S_W1I  122880u   // W1 k-pair image (16384)
#define S_W2I  139264u
#define S_CB   155648u   // b1(64) b2(64) fcw(64)
#define S_R    156416u   // cold-path fc partials (5120)
#define DYNSMEM 161536

typedef unsigned long long ull;

// ---------------- device scratch (static, zero-initialized) ----------------
__device__ float g_wE[EMAX];
__device__ int   g_deg[NN];
__device__ float g_dinv[NN];
__device__ float g_y0[NN * 64];
__device__ float g_y1[NN * 64];
__device__ float g_acc[NN * 64];
__device__ float g_h[NN * 64];
__device__ unsigned g_bar_cnt;
__device__ volatile unsigned g_bar_gen;

__device__ __constant__ float c_binom[K1][K1] = {
    {1,0,0,0,0,0,0,0,0,0,0},
    {1,1,0,0,0,0,0,0,0,0,0},
    {1,2,1,0,0,0,0,0,0,0,0},
    {1,3,3,1,0,0,0,0,0,0,0},
    {1,4,6,4,1,0,0,0,0,0,0},
    {1,5,10,10,5,1,0,0,0,0,0},
    {1,6,15,20,15,6,1,0,0,0,0},
    {1,7,21,35,35,21,7,1,0,0,0},
    {1,8,28,56,70,56,28,8,1,0,0},
    {1,9,36,84,126,126,84,36,9,1,0},
    {1,10,45,120,210,252,210,120,45,10,1}
};

// ---------------------------- PTX helpers -----------------------------------
__device__ __forceinline__ ull ffma2(ull a, ull b, ull c) {
    ull d;
    asm("fma.rn.f32x2 %0, %1, %2, %3;" : "=l"(d) : "l"(a), "l"(b), "l"(c));
    return d;
}
__device__ __forceinline__ ull pack2(float lo, float hi) {
    ull d;
    asm("mov.b64 %0, {%1, %2};" : "=l"(d) : "f"(lo), "f"(hi));
    return d;
}
__device__ __forceinline__ float2 unpack2(ull v) {
    float lo, hi;
    asm("mov.b64 {%0, %1}, %2;" : "=f"(lo), "=f"(hi) : "l"(v));
    return make_float2(lo, hi);
}
__device__ __forceinline__ float hsum2(ull v) {
    float a, b;
    asm("mov.b64 {%0, %1}, %2;" : "=f"(a), "=f"(b) : "l"(v));
    return a + b;
}
__device__ __forceinline__ void lds_2x64(ull &a, ull &b, unsigned addr) {
    asm volatile("ld.shared.v2.u64 {%0, %1}, [%2];" : "=l"(a), "=l"(b) : "r"(addr));
}
__device__ __forceinline__ ull lds64(unsigned addr) {
    ull v;
    asm volatile("ld.shared.u64 %0, [%1];" : "=l"(v) : "r"(addr));
    return v;
}
__device__ __forceinline__ void sts64(unsigned addr, ull v) {
    asm volatile("st.shared.u64 [%0], %1;" :: "r"(addr), "l"(v) : "memory");
}
__device__ __forceinline__ void sts32(unsigned addr, float v) {
    asm volatile("st.shared.f32 [%0], %1;" :: "r"(addr), "f"(v) : "memory");
}
__device__ __forceinline__ void sts_v4(unsigned addr, float a, float b, float c, float d) {
    asm volatile("st.shared.v4.f32 [%0], {%1, %2, %3, %4};"
                 :: "r"(addr), "f"(a), "f"(b), "f"(c), "f"(d) : "memory");
}
__device__ __forceinline__ void cp16(unsigned dst, const float* src) {
    asm volatile("cp.async.ca.shared.global [%0], [%1], 16;" :: "r"(dst), "l"(src) : "memory");
}
__device__ __forceinline__ void cp_commit() {
    asm volatile("cp.async.commit_group;" ::: "memory");
}

// ---------------------------------------------------------------------------
// Grid barrier over exactly NBLK blocks (one wave). Cold path only.
// ---------------------------------------------------------------------------
__device__ __forceinline__ void gbar() {
    __syncthreads();
    if (threadIdx.x == 0) {
        unsigned gen = g_bar_gen;
        __threadfence();
        if (atomicAdd(&g_bar_cnt, 1u) == (unsigned)(NBLK - 1)) {
            g_bar_cnt = 0u;
            __threadfence();
            g_bar_gen = gen + 1u;
        } else {
            while (g_bar_gen == gen) { }
            __threadfence();
        }
    }
    __syncthreads();
}

// ---------------------------------------------------------------------------
// Bernstein -> monomial coefficients (exact dyadic arithmetic); tid<32 lanes.
// ---------------------------------------------------------------------------
__device__ __forceinline__ void compute_coeffs(const float* __restrict__ coe,
                                               float* s_a, int* s_need, int tid) {
    if (tid < 32) {
        int m = tid;
        float a = 0.0f;
        if (m <= KK) {
            for (int j = 0; j <= KK; j++) {
                float cj = coe[j];
                cj = cj > 0.0f ? cj : 0.0f;
                float Bv = 0.0f;
                for (int p = 0; p <= j && p <= m; p++) {
                    int q = m - p;
                    if (q > KK - j) continue;
                    float t = c_binom[j][p] * c_binom[KK - j][q];
                    Bv += (p & 1) ? -t : t;
                }
                a += cj * (c_binom[KK][j] * (1.0f / 1024.0f)) * Bv;
            }
            s_a[m] = a;
        }
        unsigned msk = __ballot_sync(0xffffffffu, (m >= 1 && m <= KK && a != 0.0f));
        if (m == 0) *s_need = msk ? 1 : 0;
    }
}

// ---------------------------------------------------------------------------
// Staging helpers.
// ---------------------------------------------------------------------------
__device__ __forceinline__ void stage_x(const float* __restrict__ X, int row0,
                                        unsigned sxb, int tid) {
    {
        int row = tid >> 4, ch = tid & 15;
        cp16(sxb + row * 256 + ch * 16, X + (row0 + row) * 64 + ch * 4);
    }
    if (tid < 128) {
        int q = tid + NTHR;
        int row = q >> 4, ch = q & 15;
        cp16(sxb + row * 256 + ch * 16, X + (row0 + row) * 64 + ch * 4);
    }
    cp_commit();
}
__device__ __forceinline__ void stage_w_image(const float* __restrict__ W, float s,
                                              unsigned base, int tid) {
#pragma unroll
    for (int it = 0; it < 4; it++) {
        int idx = tid + it * NTHR;
        int j2 = idx >> 6, c = idx & 63;
        sts64(base + (unsigned)idx * 8u,
              pack2(W[2 * j2 * 64 + c] * s, W[(2 * j2 + 1) * 64 + c] * s));
    }
}

// ---------------------------------------------------------------------------
// Fast-path core: 4 cols x 10 rows x one k-quarter (16 k).
// Per row: 4 broadcast LDS.128 + 32 ffma2 (8:1 FMA:LDS).
// wr[c4*8 + jj] = W k-pair (global pair kq*8+jj) for column 4cg+c4.
// ---------------------------------------------------------------------------
__device__ __forceinline__ void core10q(unsigned xrow, const ull wr[32],
                                        unsigned pout) {
#pragma unroll 2
    for (int r = 0; r < 10; r++) {
        ull a0 = 0ull, a1 = 0ull, a2 = 0ull, a3 = 0ull;
#pragma unroll
        for (int jp = 0; jp < 2; jp++) {
            ull x01, x23, x45, x67;
            lds_2x64(x01, x23, xrow + (unsigned)(r * 256 + jp * 32));
            lds_2x64(x45, x67, xrow + (unsigned)(r * 256 + jp * 32 + 16));
            const int j0 = 4 * jp;
            a0 = ffma2(x01, wr[0 * 8 + j0 + 0], a0);
            a1 = ffma2(x01, wr[1 * 8 + j0 + 0], a1);
            a2 = ffma2(x01, wr[2 * 8 + j0 + 0], a2);
            a3 = ffma2(x01, wr[3 * 8 + j0 + 0], a3);
            a0 = ffma2(x23, wr[0 * 8 + j0 + 1], a0);
            a1 = ffma2(x23, wr[1 * 8 + j0 + 1], a1);
            a2 = ffma2(x23, wr[2 * 8 + j0 + 1], a2);
            a3 = ffma2(x23, wr[3 * 8 + j0 + 1], a3);
            a0 = ffma2(x45, wr[0 * 8 + j0 + 2], a0);
            a1 = ffma2(x45, wr[1 * 8 + j0 + 2], a1);
            a2 = ffma2(x45, wr[2 * 8 + j0 + 2], a2);
            a3 = ffma2(x45, wr[3 * 8 + j0 + 2], a3);
            a0 = ffma2(x67, wr[0 * 8 + j0 + 3], a0);
            a1 = ffma2(x67, wr[1 * 8 + j0 + 3], a1);
            a2 = ffma2(x67, wr[2 * 8 + j0 + 3], a2);
            a3 = ffma2(x67, wr[3 * 8 + j0 + 3], a3);
        }
        sts_v4(pout + (unsigned)(r * 256),
               hsum2(a0), hsum2(a1), hsum2(a2), hsum2(a3));
    }
}

// ---------------------------------------------------------------------------
// Cold path (arbitrary coe): R13 machinery, __noinline__.
// ---------------------------------------------------------------------------
__device__ __noinline__ void poly_phase(const float* __restrict__ xin,
                                        const int* __restrict__ src,
                                        const int* __restrict__ dst,
                                        int e, int gt, int gsz, const float* sa) {
    float a0v = sa[0];
    for (int i = gt; i < NN * 64; i += gsz) g_acc[i] = a0v * xin[i];
    const float* yin = xin;
    float* yout = g_y0;
    float* yoth = g_y1;
    for (int m = 1; m <= KK; m++) {
        for (int i = gt; i < NN * 64; i += gsz) yout[i] = 0.0f;
        gbar();
        int tot = e * 32;
        for (int t = gt; t < tot; t += gsz) {
            int ed = t >> 5;
            int l = (t & 31) << 1;
            float w = g_wE[ed];
            int s = src[ed], d = dst[ed];
            float2 v = *(const float2*)(yin + s * 64 + l);
            atomicAdd(&yout[d * 64 + l],     w * v.x);
            atomicAdd(&yout[d * 64 + l + 1], w * v.y);
        }
        gbar();
        float am = sa[m];
        for (int i = gt; i < NN * 64; i += gsz) g_acc[i] += am * yout[i];
        yin = yout;
        float* t2 = yout; yout = yoth; yoth = t2;
    }
    gbar();
}

__device__ __noinline__ void gemm_pass_cold(
    const float* __restrict__ Xsrc,
    const float* __restrict__ W,
    const float* __restrict__ bias,
    const float* __restrict__ fcw, const float* __restrict__ fcb,
    float* __restrict__ Hout, float* __restrict__ out,
    int mode, unsigned sb, float* __restrict__ sred, int tid)
{
    const int cp = tid & 31;
    const int h  = (tid >> 5) & 1;
    const int rg = tid >> 6;

    stage_w_image(W, 1.0f, sb + S_W1I, tid);
    __syncthreads();

    ull wr[32];
    {
        unsigned wb = sb + S_W1I + (unsigned)(h * 16) * 512u + (unsigned)cp * 16u;
#pragma unroll
        for (int j = 0; j < 8; j++) {
            lds_2x64(wr[4 * j + 0], wr[4 * j + 1], wb + (unsigned)(2 * j) * 512u);
            lds_2x64(wr[4 * j + 2], wr[4 * j + 3], wb + (unsigned)(2 * j + 1) * 512u);
        }
    }
    const float2 bv = ((const float2*)bias)[cp];
    float2 fwv = make_float2(0.0f, 0.0f);
    float fb = 0.0f;
    if (mode) { fwv = ((const float2*)fcw)[cp]; fb = fcb[0]; }

    int t = blockIdx.x;
    int p = 0;
    if (t < NTILES) stage_x(Xsrc, t * RT, sb + S_X0, tid);
    for (; t < NTILES; t += NBLK) {
        int tn = t + NBLK;
        bool hn = tn < NTILES;
        if (hn) stage_x(Xsrc, tn * RT, sb + (p ? S_X0 : S_X1), tid);
        if (hn) asm volatile("cp.async.wait_group 1;" ::: "memory");
        else    asm volatile("cp.async.wait_group 0;" ::: "memory");
        __syncthreads();

        const unsigned xrow = sb + (p ? S_X1 : S_X0)
                            + (unsigned)(rg * 5) * 256u + (unsigned)(h * 128);
        ull acc[10];
#pragma unroll
        for (int i = 0; i < 10; i++) acc[i] = 0ull;
#pragma unroll
        for (int j = 0; j < 8; j++) {
#pragma unroll
            for (int r = 0; r < 5; r++) {
                ull x01, x23;
                lds_2x64(x01, x23, xrow + r * 256 + j * 16);
                acc[r * 2 + 0] = ffma2(x01, wr[4 * j + 0], acc[r * 2 + 0]);
                acc[r * 2 + 1] = ffma2(x01, wr[4 * j + 1], acc[r * 2 + 1]);
                acc[r * 2 + 0] = ffma2(x23, wr[4 * j + 2], acc[r * 2 + 0]);
                acc[r * 2 + 1] = ffma2(x23, wr[4 * j + 3], acc[r * 2 + 1]);
            }
        }
        if (h) {
#pragma unroll
            for (int r = 0; r < 5; r++)
                sts64(sb + S_PA + (unsigned)((rg * 5 + r) * 64 + 2 * cp) * 4u,
                      pack2(hsum2(acc[r * 2 + 0]), hsum2(acc[r * 2 + 1])));
        }
        __syncthreads();
        if (!h) {
#pragma unroll
            for (int r = 0; r < 5; r++) {
                float2 o = unpack2(lds64(sb + S_PA
                              + (unsigned)((rg * 5 + r) * 64 + 2 * cp) * 4u));
                float sx = hsum2(acc[r * 2 + 0]) + o.x + bv.x;
                float sy = hsum2(acc[r * 2 + 1]) + o.y + bv.y;
                if (mode == 0) {
                    float2 hv;
                    hv.x = fmaxf(sx, 0.0f);
                    hv.y = fmaxf(sy, 0.0f);
                    *(float2*)(Hout + (size_t)(t * RT + rg * 5 + r) * 64 + 2 * cp) = hv;
                } else {
                    float pr = fmaxf(sx, 0.0f) * fwv.x + fmaxf(sy, 0.0f) * fwv.y;
                    sts32(sb + S_R + (unsigned)((rg * 5 + r) * 32 + cp) * 4u, pr);
                }
            }
        }
        if (mode) {
            __syncthreads();
            if (tid < RT) {
                const float4* rp = (const float4*)(sred + tid * 32);
                float s = fb;
#pragma unroll
                for (int q4 = 0; q4 < 8; q4++) {
                    float4 v = rp[q4];
                    s += v.x + v.y + v.z + v.w;
                }
                out[t * RT + tid] = s;
            }
        }
        __syncthreads();
        p ^= 1;
    }
}

__device__ __noinline__ void cold_path(
    const float* x, const int* src, const int* dst, int e,
    const float* W1, const float* b1,
    const float* W2, const float* b2,
    const float* fcw, const float* fcb,
    float* out, const float* s_a, unsigned sb, float* sred)
{
    const int tid = threadIdx.x;
    const int gt  = blockIdx.x * NTHR + tid;
    const int gsz = NBLK * NTHR;

    for (int i = gt; i < NN; i += gsz) g_deg[i] = 0;
    gbar();
    for (int t = gt; t < e; t += gsz) atomicAdd(&g_deg[src[t]], 1);
    gbar();
    for (int i = gt; i < NN; i += gsz) {
        int d = g_deg[i];
        g_dinv[i] = d > 0 ? rsqrtf((float)d) : 0.0f;
    }
    gbar();
    for (int t = gt; t < e; t += gsz) g_wE[t] = g_dinv[src[t]] * g_dinv[dst[t]];
    gbar();

    poly_phase(x, src, dst, e, gt, gsz, s_a);
    gemm_pass_cold(g_acc, W1, b1, fcw, fcb, g_h, out, 0, sb, sred, tid);
    gbar();
    poly_phase(g_h, src, dst, e, gt, gsz, s_a);
    gemm_pass_cold(g_acc, W2, b2, fcw, fcb, (float*)0, out, 1, sb, sred, tid);
}

// ---------------------------------------------------------------------------
// Kernel: single launch, persistent NBLK blocks.
// Fast path: warp-specialized (R13 structure) with 8:1 FMA:LDS core.
//   A warps (0-7):  core10q(tile t, W1) -> PA planes; bar1; combine -> H[p]
//   B warps (8-15): core10q(H[p^1], W2) -> PB planes; bar2; fc -> out
// Thread geometry per group: cg = col quad (16), kq = k-quarter (4),
//   rg = row group of 10 (4).
// ---------------------------------------------------------------------------
__global__ __launch_bounds__(NTHR, 1) void bernnet(
    const float* __restrict__ x,
    const int*   __restrict__ src,
    const int*   __restrict__ dst,
    int e,
    const float* __restrict__ coe,
    const float* __restrict__ W1, const float* __restrict__ b1,
    const float* __restrict__ W2, const float* __restrict__ b2,
    const float* __restrict__ fcw, const float* __restrict__ fcb,
    float* __restrict__ out)
{
    extern __shared__ __align__(16) char dsm[];
    const unsigned sb = (unsigned)__cvta_generic_to_shared(dsm);
    __shared__ float s_a[K1];
    __shared__ int   s_need;

    const int tid = threadIdx.x;

    compute_coeffs(coe, s_a, &s_need, tid);
    __syncthreads();

    if (s_need) {
        cold_path(x, src, dst, e, W1, b1, W2, b2, fcw, fcb, out, s_a, sb,
                  (float*)(dsm + S_R));
        return;
    }

    // ===================== fast path: p(A) = a0*I ==========================
    const float a0 = s_a[0];

    stage_w_image(W1, a0, sb + S_W1I, tid);
    stage_w_image(W2, a0, sb + S_W2I, tid);
    {
        float* scb = (float*)(dsm + S_CB);
        if (tid < 64)       scb[tid] = b1[tid];
        else if (tid < 128) scb[tid] = b2[tid - 64];
        else if (tid < 192) scb[tid] = fcw[tid - 128];
    }
    __syncthreads();

    const int group = tid >> 8;            // 0: layer1 (A), 1: layer2+fc (B)
    const int gt    = tid & 255;
    const int cg    = gt & 15;              // col quad: cols 4cg..4cg+3
    const int kq    = (gt >> 4) & 3;        // k-quarter: k = 16kq..16kq+15
    const int rg    = gt >> 6;              // rows rg*10..rg*10+9
    const int lane  = tid & 31;
    const int gw    = (tid >> 5) & 7;       // warp within group

    // W registers: 4 cols x 8 local k-pairs
    ull wr[32];
    {
        unsigned wib = sb + (group ? S_W2I : S_W1I);
#pragma unroll
        for (int c4 = 0; c4 < 4; c4++)
#pragma unroll
            for (int jj = 0; jj < 8; jj++)
                wr[c4 * 8 + jj] = lds64(wib +
                    (unsigned)(((kq * 8 + jj) * 64 + (4 * cg + c4)) * 8));
    }
    const float2* scb2 = (const float2*)(dsm + S_CB);
    const float fb = fcb[0];
    const unsigned coreoff = (unsigned)(rg * 10) * 256u + (unsigned)(kq * 64);
    const unsigned pwoff   = (unsigned)(kq * 10240) + (unsigned)(rg * 10) * 256u
                           + (unsigned)(cg * 16);

    int t = blockIdx.x, tprev = -1, p = 0;
    stage_x(x, t * RT, sb + S_X0, tid);

    for (;;) {
        const bool hasA = (t < NTILES);
        const bool hasB = (tprev >= 0);
        if (!hasA && !hasB) break;

        asm volatile("cp.async.wait_group 0;" ::: "memory");
        __syncthreads();
        const int tn = t + NBLK;
        if (tn < NTILES) stage_x(x, tn * RT, sb + (p ? S_X0 : S_X1), tid);

        if (group == 0) {
            if (hasA) {
                core10q(sb + (p ? S_X1 : S_X0) + coreoff, wr, sb + S_PA + pwoff);
                asm volatile("bar.sync 1, 256;" ::: "memory");
                const unsigned hplane = sb + (p ? S_H1 : S_H0);
#pragma unroll
                for (int j = 0; j < 5; j++) {
                    unsigned o = (unsigned)((5 * gw + j) * 256 + lane * 8);
                    float2 s0 = unpack2(lds64(sb + S_PA + o));
                    float2 s1 = unpack2(lds64(sb + S_PA + 10240u + o));
                    float2 s2 = unpack2(lds64(sb + S_PA + 20480u + o));
                    float2 s3 = unpack2(lds64(sb + S_PA + 30720u + o));
                    float2 b = scb2[lane];
                    sts64(hplane + o,
                          pack2(fmaxf(s0.x + s1.x + s2.x + s3.x + b.x, 0.0f),
                                fmaxf(s0.y + s1.y + s2.y + s3.y + b.y, 0.0f)));
                }
            }
        } else {
            if (hasB) {
                core10q(sb + (p ? S_H0 : S_H1) + coreoff, wr, sb + S_PB + pwoff);
                asm volatile("bar.sync 2, 256;" ::: "memory");
                float pr[5];
#pragma unroll
                for (int j = 0; j < 5; j++) {
                    unsigned o = (unsigned)((5 * gw + j) * 256 + lane * 8);
                    float2 s0 = unpack2(lds64(sb + S_PB + o));
                    float2 s1 = unpack2(lds64(sb + S_PB + 10240u + o));
                    float2 s2 = unpack2(lds64(sb + S_PB + 20480u + o));
                    float2 s3 = unpack2(lds64(sb + S_PB + 30720u + o));
                    float2 b = scb2[32 + lane];
                    float2 fw = scb2[64 + lane];
                    pr[j] = fmaxf(s0.x + s1.x + s2.x + s3.x + b.x, 0.0f) * fw.x
                          + fmaxf(s0.y + s1.y + s2.y + s3.y + b.y, 0.0f) * fw.y;
                }
#pragma unroll
                for (int off = 16; off; off >>= 1)
#pragma unroll
                    for (int j = 0; j < 5; j++)
                        pr[j] += __shfl_xor_sync(0xffffffffu, pr[j], off);
                if (lane == 0) {
#pragma unroll
                    for (int j = 0; j < 5; j++)
                        out[tprev * RT + 5 * gw + j] = pr[j] + fb;
                }
            }
        }
        tprev = hasA ? t : -1;
        t = tn;
        p ^= 1;
    }
}

// ---------------------------------------------------------------------------
extern "C" void kernel_launch(void* const* d_in, const int* in_sizes, int n_in,
                              void* d_out, int out_size) {
    const float* x   = (const float*)d_in[0];
    const int*   ei  = (const int*)d_in[1];
    const float* coe = (const float*)d_in[2];
    const float* W1  = (const float*)d_in[3];
    const float* b1  = (const float*)d_in[4];
    const float* W2  = (const float*)d_in[5];
    const float* b2  = (const float*)d_in[6];
    const float* fcw = (const float*)d_in[7];
    const float* fcb = (const float*)d_in[8];
    float* out = (float*)d_out;

    int e = in_sizes[1] / 2;
    const int* src = ei;
    const int* dst = ei + e;

    static int smem_set = 0;
    if (!smem_set) {
        cudaFuncSetAttribute(bernnet, cudaFuncAttributeMaxDynamicSharedMemorySize,
                             DYNSMEM);
        smem_set = 1;
    }

    bernnet<<<NBLK, NTHR, DYNSMEM>>>(x, src, dst, e, coe,
                                     W1, b1, W2, b2, fcw, fcb, out);
}